// round 1
// baseline (speedup 1.0000x reference)
#include <cuda_runtime.h>
#include <math.h>
#include <stdint.h>

// ---- problem constants ----
#define MD 2
#define MHW 7
#define NWIN 98           // 2*7*7 tokens per window
#define NH 3              // heads
#define HD 32             // head dim
#define CD 96             // channels
#define DD 16
#define HH 112
#define WW2 112
#define NWX 2048          // windows per batch: 8*16*16
#define BATCH 2
#define BTOT (BATCH*NWX)      // 4096
#define MTOT (BTOT*NWIN)      // 401408
#define LTOT (DD*HH*WW2)      // 200704
#define SCALE 0.17677669529663689f   // 32^-0.5

// ---- scratch (device globals: no allocation allowed) ----
__device__ float g_xw[(size_t)MTOT*CD];          // normalized, windowed x
__device__ float g_q[(size_t)BTOT*NH*NWIN*HD];   // (B_, h, N, hd), q pre-scaled
__device__ float g_k[(size_t)BTOT*NH*NWIN*HD];
__device__ float g_v[(size_t)BTOT*NH*NWIN*HD];
__device__ float g_ao[(size_t)MTOT*CD];          // attn output, (B_*N, C)
__device__ float g_y[(size_t)MTOT*CD];           // proj output scattered back to (B,L,C)
__device__ float g_bias[NH*NWIN*NWIN];           // rel-pos bias (h, N, N)

// ============ K0: build relative position bias table ============
__global__ void bias_kernel(const float* __restrict__ table) {
    int idx = blockIdx.x * blockDim.x + threadIdx.x;
    if (idx >= NH * NWIN * NWIN) return;
    int head = idx / (NWIN * NWIN);
    int r = idx % (NWIN * NWIN);
    int n = r / NWIN, m = r % NWIN;
    int d1 = n / 49, h1 = (n % 49) / 7, w1 = n % 7;
    int d2 = m / 49, h2 = (m % 49) / 7, w2 = m % 7;
    int t = (d1 - d2 + 1) * 169 + (h1 - h2 + 6) * 13 + (w1 - w2 + 6);
    g_bias[idx] = table[t * NH + head];
}

// ============ K1: LayerNorm + shift + window partition ============
// one warp per OUTPUT windowed token; gathers from rolled source location
__global__ void ln_part_kernel(const float* __restrict__ x,
                               const float* __restrict__ nw,
                               const float* __restrict__ nb) {
    int warp = (blockIdx.x * blockDim.x + threadIdx.x) >> 5;
    int lane = threadIdx.x & 31;
    if (warp >= MTOT) return;
    int b_ = warp / NWIN, n = warp % NWIN;
    int b = b_ >> 11;             // /NWX
    int widx = b_ & (NWX - 1);
    int wd = widx >> 8, wh = (widx >> 4) & 15, ww = widx & 15;
    int nd = n / 49, nr = n % 49, nh2 = nr / 7, nw2 = nr % 7;
    int dp = wd * 2 + nd, hp = wh * 7 + nh2, wp = ww * 7 + nw2;
    int d = dp + 1; if (d >= DD) d -= DD;
    int h = hp + 3; if (h >= HH) h -= HH;
    int w = wp + 3; if (w >= WW2) w -= WW2;
    size_t src = ((size_t)b * LTOT + (size_t)(d * (HH * WW2) + h * WW2 + w)) * CD;
    float v0 = x[src + lane], v1 = x[src + 32 + lane], v2 = x[src + 64 + lane];
    float s = v0 + v1 + v2;
    float ss = v0 * v0 + v1 * v1 + v2 * v2;
    #pragma unroll
    for (int o = 16; o; o >>= 1) {
        s  += __shfl_xor_sync(0xffffffffu, s, o);
        ss += __shfl_xor_sync(0xffffffffu, ss, o);
    }
    float mean = s * (1.0f / 96.0f);
    float var = ss * (1.0f / 96.0f) - mean * mean;
    float rs = rsqrtf(var + 1e-5f);
    size_t dst = (size_t)warp * CD;
    g_xw[dst + lane]      = (v0 - mean) * rs * nw[lane]      + nb[lane];
    g_xw[dst + 32 + lane] = (v1 - mean) * rs * nw[lane + 32] + nb[lane + 32];
    g_xw[dst + 64 + lane] = (v2 - mean) * rs * nw[lane + 64] + nb[lane + 64];
}

// ============ GEMM core: C[M,96] tile = A[64,96] @ W[96,96]^T ============
// EPI 0: qkv (A=g_xw, W part=blockIdx.y, scatter to g_q/g_k/g_v, q scaled)
// EPI 1: proj (A=g_ao, scatter to g_y with window-reverse + roll)
// EPI 2: fc1  (A=g_y, out = resid + gelu(val))
template<int EPI>
__global__ void gemm96(const float* __restrict__ Wt,
                       const float* __restrict__ bias,
                       const float* __restrict__ resid,
                       float* __restrict__ out) {
    __shared__ float As[32 * 64];   // [kk][r]
    __shared__ float Ws[32 * 96];   // [kk][c]
    const float* A = (EPI == 0) ? g_xw : (EPI == 1) ? g_ao : g_y;
    int rowbase = blockIdx.x * 64;
    int p = blockIdx.y;
    int tid = threadIdx.x;
    int tx = tid & 15, ty = tid >> 4;
    float acc[4][6];
    #pragma unroll
    for (int i = 0; i < 4; i++)
        #pragma unroll
        for (int j = 0; j < 6; j++) acc[i][j] = 0.0f;

    for (int kb = 0; kb < 96; kb += 32) {
        for (int idx = tid; idx < 2048; idx += 256) {
            int r = idx >> 5, kk = idx & 31;
            As[kk * 64 + r] = A[(size_t)(rowbase + r) * 96 + kb + kk];
        }
        for (int idx = tid; idx < 3072; idx += 256) {
            int c = idx >> 5, kk = idx & 31;
            Ws[kk * 96 + c] = Wt[(size_t)(p * 96 + c) * 96 + kb + kk];
        }
        __syncthreads();
        #pragma unroll
        for (int kk = 0; kk < 32; kk++) {
            float af[4], wf[6];
            #pragma unroll
            for (int i = 0; i < 4; i++) af[i] = As[kk * 64 + ty * 4 + i];
            #pragma unroll
            for (int j = 0; j < 6; j++) wf[j] = Ws[kk * 96 + tx * 6 + j];
            #pragma unroll
            for (int i = 0; i < 4; i++)
                #pragma unroll
                for (int j = 0; j < 6; j++) acc[i][j] += af[i] * wf[j];
        }
        __syncthreads();
    }

    #pragma unroll
    for (int i = 0; i < 4; i++) {
        int m = rowbase + ty * 4 + i;
        int b_ = m / NWIN, n = m % NWIN;
        #pragma unroll
        for (int j = 0; j < 6; j++) {
            int c = tx * 6 + j;
            if (EPI == 0) {
                float v = acc[i][j] + bias[p * 96 + c];
                if (p == 0) v *= SCALE;
                int head = c >> 5, wd = c & 31;
                size_t dst = (((size_t)b_ * NH + head) * NWIN + n) * HD + wd;
                if (p == 0) g_q[dst] = v;
                else if (p == 1) g_k[dst] = v;
                else g_v[dst] = v;
            } else if (EPI == 1) {
                float v = acc[i][j] + bias[c];
                int b = b_ >> 11;
                int widx = b_ & (NWX - 1);
                int wd = widx >> 8, wh = (widx >> 4) & 15, ww = widx & 15;
                int nd = n / 49, nr = n % 49, nh2 = nr / 7, nw2 = nr % 7;
                int dp = wd * 2 + nd, hp = wh * 7 + nh2, wp = ww * 7 + nw2;
                int d = dp + 1; if (d >= DD) d -= DD;
                int h = hp + 3; if (h >= HH) h -= HH;
                int w = wp + 3; if (w >= WW2) w -= WW2;
                size_t dst = ((size_t)b * LTOT + (size_t)(d * (HH * WW2) + h * WW2 + w)) * CD + c;
                g_y[dst] = v;
            } else {
                float v = acc[i][j] + bias[c];
                float ge = 0.5f * v * (1.0f + erff(v * 0.70710678118654752f));
                size_t o = (size_t)m * CD + c;
                out[o] = resid[o] + ge;
            }
        }
    }
}

// ============ K3: fused window attention, one block per (window, head) ============
// smem: qT[32][98] kT[32][98] vs[98][32] Ss[98][99]  = 76440 B (dynamic)
#define ATTN_SMEM ((3 * 32 * 98 + 98 * 99) * 4)
__global__ void attn_kernel(const float* __restrict__ mask) {
    extern __shared__ float sm[];
    float* qT = sm;                   // [32][98]
    float* kT = qT + 32 * 98;         // [32][98]
    float* vs = kT + 32 * 98;         // [98][32]
    float* Ss = vs + 98 * 32;         // [98][99] pitch 99 (conflict-avoid)
    int b_ = blockIdx.x;
    int head = blockIdx.y;
    int tid = threadIdx.x;
    size_t base = ((size_t)b_ * NH + head) * (size_t)(NWIN * HD);

    for (int idx = tid; idx < NWIN * HD; idx += 224) {
        int n = idx >> 5, c = idx & 31;
        float qv = g_q[base + idx];
        float kv = g_k[base + idx];
        qT[c * 98 + n] = qv;
        kT[c * 98 + n] = kv;
        vs[idx] = g_v[base + idx];
    }
    __syncthreads();

    // S = q k^T : 14x14 thread grid, 7x7 register tile each
    if (tid < 196) {
        int i = tid / 14, j = tid % 14;
        float acc[7][7];
        #pragma unroll
        for (int a = 0; a < 7; a++)
            #pragma unroll
            for (int b = 0; b < 7; b++) acc[a][b] = 0.0f;
        #pragma unroll 4
        for (int k = 0; k < 32; k++) {
            float qf[7], kf[7];
            #pragma unroll
            for (int a = 0; a < 7; a++) qf[a] = qT[k * 98 + i * 7 + a];
            #pragma unroll
            for (int b = 0; b < 7; b++) kf[b] = kT[k * 98 + j * 7 + b];
            #pragma unroll
            for (int a = 0; a < 7; a++)
                #pragma unroll
                for (int b = 0; b < 7; b++) acc[a][b] += qf[a] * kf[b];
        }
        #pragma unroll
        for (int a = 0; a < 7; a++)
            #pragma unroll
            for (int b = 0; b < 7; b++)
                Ss[(i * 7 + a) * 99 + j * 7 + b] = acc[a][b];
    }
    __syncthreads();

    // softmax with rel-bias + shift mask, one thread per row
    if (tid < NWIN) {
        int wmask = b_ & (NWX - 1);
        const float* brow = g_bias + head * (NWIN * NWIN) + tid * NWIN;
        const float* mrow = mask + (size_t)wmask * (NWIN * NWIN) + tid * NWIN;
        float* srow = Ss + tid * 99;
        float mx = -1e30f;
        for (int m = 0; m < NWIN; m++) {
            float v = srow[m] + brow[m] + mrow[m];
            srow[m] = v;
            mx = fmaxf(mx, v);
        }
        float sum = 0.0f;
        for (int m = 0; m < NWIN; m++) {
            float e = __expf(srow[m] - mx);
            srow[m] = e;
            sum += e;
        }
        float inv = 1.0f / sum;
        for (int m = 0; m < NWIN; m++) srow[m] *= inv;
    }
    __syncthreads();

    // O = P V : 14x16 thread grid, 7x2 register tile
    {
        int i = tid >> 4, j = tid & 15;   // i:0..13 rows*7, j:0..15 cols*2
        float acc[7][2];
        #pragma unroll
        for (int a = 0; a < 7; a++) { acc[a][0] = 0.0f; acc[a][1] = 0.0f; }
        for (int m = 0; m < NWIN; m++) {
            float v0 = vs[m * 32 + j * 2];
            float v1 = vs[m * 32 + j * 2 + 1];
            #pragma unroll
            for (int a = 0; a < 7; a++) {
                float pv = Ss[(i * 7 + a) * 99 + m];
                acc[a][0] += pv * v0;
                acc[a][1] += pv * v1;
            }
        }
        #pragma unroll
        for (int a = 0; a < 7; a++) {
            size_t o = ((size_t)b_ * NWIN + i * 7 + a) * CD + head * HD + j * 2;
            g_ao[o] = acc[a][0];
            g_ao[o + 1] = acc[a][1];
        }
    }
}

// ============ launch ============
extern "C" void kernel_launch(void* const* d_in, const int* in_sizes, int n_in,
                              void* d_out, int out_size) {
    const float* x     = (const float*)d_in[0];
    const float* mask  = (const float*)d_in[1];
    const float* n1w   = (const float*)d_in[2];
    const float* n1b   = (const float*)d_in[3];
    const float* qkvw  = (const float*)d_in[4];
    const float* qkvb  = (const float*)d_in[5];
    const float* relt  = (const float*)d_in[6];
    const float* projw = (const float*)d_in[7];
    const float* projb = (const float*)d_in[8];
    const float* fc1w  = (const float*)d_in[9];
    const float* fc1b  = (const float*)d_in[10];
    float* out = (float*)d_out;

    // opt-in >48KB dynamic smem (idempotent; ignore errors during capture)
    cudaFuncSetAttribute(attn_kernel, cudaFuncAttributeMaxDynamicSharedMemorySize, ATTN_SMEM);

    bias_kernel<<<(NH * NWIN * NWIN + 1023) / 1024, 1024>>>(relt);
    ln_part_kernel<<<MTOT / 4, 128>>>(x, n1w, n1b);
    gemm96<0><<<dim3(MTOT / 64, 3), 256>>>(qkvw, qkvb, nullptr, nullptr);
    attn_kernel<<<dim3(BTOT, NH), 224, ATTN_SMEM>>>(mask);
    gemm96<1><<<dim3(MTOT / 64, 1), 256>>>(projw, projb, nullptr, nullptr);
    gemm96<2><<<dim3(MTOT / 64, 1), 256>>>(fc1w, fc1b, x, out);
}

// round 2
// speedup vs baseline: 2.0680x; 2.0680x over previous
#include <cuda_runtime.h>
#include <math.h>
#include <stdint.h>

// ---- problem constants ----
#define NWIN 98           // 2*7*7 tokens per window
#define NH 3              // heads
#define HD 32             // head dim
#define CD 96             // channels
#define DD 16
#define HH 112
#define WW2 112
#define NWX 2048          // windows per batch: 8*16*16
#define BATCH 2
#define BTOT (BATCH*NWX)      // 4096
#define MTOT (BTOT*NWIN)      // 401408
#define LTOT (DD*HH*WW2)      // 200704
#define SCALE 0.17677669529663689f   // 32^-0.5

// ---- scratch (device globals: no allocation allowed) ----
__device__ float g_xw[(size_t)MTOT*CD];          // normalized, windowed x
__device__ float g_q[(size_t)BTOT*NH*NWIN*HD];   // (B_, h, N, hd), q pre-scaled
__device__ float g_k[(size_t)BTOT*NH*NWIN*HD];
__device__ float g_v[(size_t)BTOT*NH*NWIN*HD];
__device__ float g_ao[(size_t)MTOT*CD];          // attn output, (B_*N, C)
__device__ float g_y[(size_t)MTOT*CD];           // proj output scattered back to (B,L,C)
__device__ float g_bias[NH*NWIN*NWIN];           // rel-pos bias (h, N, N)

// ---- tf32 helpers ----
__device__ __forceinline__ unsigned f2tf(float x) {
    unsigned r;
    asm("cvt.rna.tf32.f32 %0, %1;" : "=r"(r) : "f"(x));
    return r;
}
__device__ __forceinline__ void mma_tf32(float* d, uint4 a, uint2 b) {
    asm volatile(
        "mma.sync.aligned.m16n8k8.row.col.f32.tf32.tf32.f32 "
        "{%0,%1,%2,%3}, {%4,%5,%6,%7}, {%8,%9}, {%0,%1,%2,%3};"
        : "+f"(d[0]), "+f"(d[1]), "+f"(d[2]), "+f"(d[3])
        : "r"(a.x), "r"(a.y), "r"(a.z), "r"(a.w), "r"(b.x), "r"(b.y));
}

// ============ K0: build relative position bias table ============
__global__ void bias_kernel(const float* __restrict__ table) {
    int idx = blockIdx.x * blockDim.x + threadIdx.x;
    if (idx >= NH * NWIN * NWIN) return;
    int head = idx / (NWIN * NWIN);
    int r = idx % (NWIN * NWIN);
    int n = r / NWIN, m = r % NWIN;
    int d1 = n / 49, h1 = (n % 49) / 7, w1 = n % 7;
    int d2 = m / 49, h2 = (m % 49) / 7, w2 = m % 7;
    int t = (d1 - d2 + 1) * 169 + (h1 - h2 + 6) * 13 + (w1 - w2 + 6);
    g_bias[idx] = table[t * NH + head];
}

// ============ K1: LayerNorm + shift + window partition ============
__global__ void ln_part_kernel(const float* __restrict__ x,
                               const float* __restrict__ nw,
                               const float* __restrict__ nb) {
    int warp = (blockIdx.x * blockDim.x + threadIdx.x) >> 5;
    int lane = threadIdx.x & 31;
    if (warp >= MTOT) return;
    int b_ = warp / NWIN, n = warp % NWIN;
    int b = b_ >> 11;
    int widx = b_ & (NWX - 1);
    int wd = widx >> 8, wh = (widx >> 4) & 15, ww = widx & 15;
    int nd = n / 49, nr = n % 49, nh2 = nr / 7, nw2 = nr % 7;
    int dp = wd * 2 + nd, hp = wh * 7 + nh2, wp = ww * 7 + nw2;
    int d = dp + 1; if (d >= DD) d -= DD;
    int h = hp + 3; if (h >= HH) h -= HH;
    int w = wp + 3; if (w >= WW2) w -= WW2;
    size_t src = ((size_t)b * LTOT + (size_t)(d * (HH * WW2) + h * WW2 + w)) * CD;
    float v0 = x[src + lane], v1 = x[src + 32 + lane], v2 = x[src + 64 + lane];
    float s = v0 + v1 + v2;
    float ss = v0 * v0 + v1 * v1 + v2 * v2;
    #pragma unroll
    for (int o = 16; o; o >>= 1) {
        s  += __shfl_xor_sync(0xffffffffu, s, o);
        ss += __shfl_xor_sync(0xffffffffu, ss, o);
    }
    float mean = s * (1.0f / 96.0f);
    float var = ss * (1.0f / 96.0f) - mean * mean;
    float rs = rsqrtf(var + 1e-5f);
    size_t dst = (size_t)warp * CD;
    g_xw[dst + lane]      = (v0 - mean) * rs * nw[lane]      + nb[lane];
    g_xw[dst + 32 + lane] = (v1 - mean) * rs * nw[lane + 32] + nb[lane + 32];
    g_xw[dst + 64 + lane] = (v2 - mean) * rs * nw[lane + 64] + nb[lane + 64];
}

// ============ tf32 tensor-core GEMM: 128x96 block, out = A[128,96] @ W[96,96]^T ============
// EPI 0: qkv  (A=g_xw, part=blockIdx.y, scatter q/k/v head-major, q pre-scaled)
// EPI 1: proj (A=g_ao, scatter to g_y with window-reverse + roll)
// EPI 2: fc1  (A=g_y, out = resid + gelu(val))
// smem: packed MMA fragments.
//   sA: [8 mtile][12 kt][32 lane][4]  u32 = 49152 B
//   sB: [12 nt ][12 kt][32 lane][2]  u32 = 36864 B
#define GEMM_SMEM (49152 + 36864)
template<int EPI>
__global__ __launch_bounds__(256, 2)
void gemm_tc(const float* __restrict__ Wt,
             const float* __restrict__ bias,
             const float* __restrict__ resid,
             float* __restrict__ out) {
    extern __shared__ unsigned smu[];
    unsigned* sA = smu;              // 12288 u32
    unsigned* sB = smu + 12288;      // 9216 u32
    const float* A = (EPI == 0) ? g_xw : (EPI == 1) ? g_ao : g_y;
    int rowbase = blockIdx.x * 128;
    int p = blockIdx.y;
    int tid = threadIdx.x;
    int w = tid >> 5, lane = tid & 31;
    int g = lane >> 2, tig = lane & 3;

    // ---- pack A: 128 rows x 96 k, float4 loads ----
    {
        const float4* A4 = (const float4*)(A + (size_t)rowbase * 96);
        #pragma unroll
        for (int it = 0; it < 12; it++) {
            int idx = tid + it * 256;          // 3072 float4 total
            int r = idx / 24, k4 = idx % 24;
            float4 v = A4[r * 24 + k4];
            int mtile = r >> 4, mloc = r & 15;
            int gg = mloc & 7;
            int kbase = k4 * 4;
            int kt = kbase >> 3;
            int slotbase = ((kbase & 4) ? 2 : 0) | (mloc >> 3);
            unsigned* dst = sA + ((mtile * 12 + kt) * 32) * 4 + slotbase;
            dst[(gg * 4 + 0) * 4] = f2tf(v.x);
            dst[(gg * 4 + 1) * 4] = f2tf(v.y);
            dst[(gg * 4 + 2) * 4] = f2tf(v.z);
            dst[(gg * 4 + 3) * 4] = f2tf(v.w);
        }
    }
    // ---- pack B: 96 rows (out channels) x 96 k ----
    {
        const float4* B4 = (const float4*)(Wt + (size_t)p * 96 * 96);
        #pragma unroll
        for (int it = 0; it < 9; it++) {
            int idx = tid + it * 256;          // 2304 float4 total
            int c = idx / 24, k4 = idx % 24;
            float4 v = B4[c * 24 + k4];
            int nt = c >> 3, gg = c & 7;
            int kbase = k4 * 4;
            int kt = kbase >> 3;
            int slot = (kbase & 4) ? 1 : 0;
            unsigned* dst = sB + ((nt * 12 + kt) * 32) * 2 + slot;
            dst[(gg * 4 + 0) * 2] = f2tf(v.x);
            dst[(gg * 4 + 1) * 2] = f2tf(v.y);
            dst[(gg * 4 + 2) * 2] = f2tf(v.z);
            dst[(gg * 4 + 3) * 2] = f2tf(v.w);
        }
    }
    __syncthreads();

    float d[12][4];
    #pragma unroll
    for (int nt = 0; nt < 12; nt++)
        #pragma unroll
        for (int r = 0; r < 4; r++) d[nt][r] = 0.0f;

    const uint4* a4 = (const uint4*)sA;
    const uint2* b2 = (const uint2*)sB;
    #pragma unroll
    for (int kt = 0; kt < 12; kt++) {
        uint4 af = a4[(w * 12 + kt) * 32 + lane];
        #pragma unroll
        for (int nt = 0; nt < 12; nt++) {
            uint2 bf = b2[(nt * 12 + kt) * 32 + lane];
            mma_tf32(d[nt], af, bf);
        }
    }

    // ---- epilogue ----
    #pragma unroll
    for (int nt = 0; nt < 12; nt++) {
        #pragma unroll
        for (int rr = 0; rr < 4; rr++) {
            int m = rowbase + w * 16 + g + ((rr >> 1) << 3);
            int c = nt * 8 + tig * 2 + (rr & 1);
            int b_ = m / NWIN, n = m % NWIN;
            if (EPI == 0) {
                float v = d[nt][rr] + bias[p * 96 + c];
                if (p == 0) v *= SCALE;
                int head = c >> 5, wd = c & 31;
                size_t dst = (((size_t)b_ * NH + head) * NWIN + n) * HD + wd;
                if (p == 0) g_q[dst] = v;
                else if (p == 1) g_k[dst] = v;
                else g_v[dst] = v;
            } else if (EPI == 1) {
                float v = d[nt][rr] + bias[c];
                int b = b_ >> 11;
                int widx = b_ & (NWX - 1);
                int wd = widx >> 8, wh = (widx >> 4) & 15, ww = widx & 15;
                int nd = n / 49, nr = n % 49, nh2 = nr / 7, nw2 = nr % 7;
                int dp = wd * 2 + nd, hp = wh * 7 + nh2, wp = ww * 7 + nw2;
                int dd = dp + 1; if (dd >= DD) dd -= DD;
                int hh = hp + 3; if (hh >= HH) hh -= HH;
                int ww3 = wp + 3; if (ww3 >= WW2) ww3 -= WW2;
                size_t dst = ((size_t)b * LTOT +
                              (size_t)(dd * (HH * WW2) + hh * WW2 + ww3)) * CD + c;
                g_y[dst] = v;
            } else {
                float v = d[nt][rr] + bias[c];
                float ge = 0.5f * v * (1.0f + erff(v * 0.70710678118654752f));
                size_t o = (size_t)m * CD + c;
                out[o] = resid[o] + ge;
            }
        }
    }
}

// ============ K3: fused window attention, one block per (window, head) ============
// smem: qT[32][98] kT[32][98] vs[98][32] Ss[98][99]  = 76440 B (dynamic)
#define ATTN_SMEM ((3 * 32 * 98 + 98 * 99) * 4)
__global__ __launch_bounds__(224, 2)
void attn_kernel(const float* __restrict__ mask) {
    extern __shared__ float sm[];
    float* qT = sm;                   // [32][98]
    float* kT = qT + 32 * 98;         // [32][98]
    float* vs = kT + 32 * 98;         // [98][32]
    float* Ss = vs + 98 * 32;         // [98][99]
    int b_ = blockIdx.x;
    int head = blockIdx.y;
    int tid = threadIdx.x;
    size_t base = ((size_t)b_ * NH + head) * (size_t)(NWIN * HD);

    // ---- load q/k/v (float4 global; 784 float4 each) ----
    {
        const float4* q4 = (const float4*)(g_q + base);
        const float4* k4 = (const float4*)(g_k + base);
        const float4* v4 = (const float4*)(g_v + base);
        float4* vs4 = (float4*)vs;
        for (int i4 = tid; i4 < 784; i4 += 224) {
            int n = i4 >> 3, c = (i4 & 7) * 4;
            float4 qv = q4[i4];
            float4 kv = k4[i4];
            qT[(c + 0) * 98 + n] = qv.x;
            qT[(c + 1) * 98 + n] = qv.y;
            qT[(c + 2) * 98 + n] = qv.z;
            qT[(c + 3) * 98 + n] = qv.w;
            kT[(c + 0) * 98 + n] = kv.x;
            kT[(c + 1) * 98 + n] = kv.y;
            kT[(c + 2) * 98 + n] = kv.z;
            kT[(c + 3) * 98 + n] = kv.w;
            vs4[i4] = v4[i4];
        }
    }
    __syncthreads();

    // ---- S = q k^T (+bias +mask fused) : 14x14 grid, 7x7 register tile ----
    if (tid < 196) {
        int i = tid / 14, j = tid % 14;
        float acc[7][7];
        #pragma unroll
        for (int a = 0; a < 7; a++)
            #pragma unroll
            for (int b = 0; b < 7; b++) acc[a][b] = 0.0f;
        #pragma unroll 4
        for (int k = 0; k < 32; k++) {
            float qf[7], kf[7];
            #pragma unroll
            for (int a = 0; a < 7; a++) qf[a] = qT[k * 98 + i * 7 + a];
            #pragma unroll
            for (int b = 0; b < 7; b++) kf[b] = kT[k * 98 + j * 7 + b];
            #pragma unroll
            for (int a = 0; a < 7; a++)
                #pragma unroll
                for (int b = 0; b < 7; b++) acc[a][b] += qf[a] * kf[b];
        }
        int wmask = b_ & (NWX - 1);
        const float* bb = g_bias + head * (NWIN * NWIN) + (i * 7) * NWIN + j * 7;
        const float* mm = mask + (size_t)wmask * (NWIN * NWIN) + (i * 7) * NWIN + j * 7;
        #pragma unroll
        for (int a = 0; a < 7; a++) {
            #pragma unroll
            for (int b = 0; b < 7; b++)
                Ss[(i * 7 + a) * 99 + j * 7 + b] =
                    acc[a][b] + __ldg(bb + a * NWIN + b) + __ldg(mm + a * NWIN + b);
        }
    }
    __syncthreads();

    // ---- softmax: 7 warps x 14 rows, lanes strided over 98 cols ----
    {
        int wp = tid >> 5, lane = tid & 31;
        for (int rr = 0; rr < 14; rr++) {
            int row = wp * 14 + rr;
            float* srow = Ss + row * 99;
            float v0 = srow[lane];
            float v1 = srow[lane + 32];
            float v2 = srow[lane + 64];
            float v3 = (lane < 2) ? srow[lane + 96] : -1e30f;
            float mx = fmaxf(fmaxf(v0, v1), fmaxf(v2, v3));
            #pragma unroll
            for (int o = 16; o; o >>= 1) mx = fmaxf(mx, __shfl_xor_sync(0xffffffffu, mx, o));
            v0 = __expf(v0 - mx);
            v1 = __expf(v1 - mx);
            v2 = __expf(v2 - mx);
            v3 = (lane < 2) ? __expf(v3 - mx) : 0.0f;
            float s = v0 + v1 + v2 + v3;
            #pragma unroll
            for (int o = 16; o; o >>= 1) s += __shfl_xor_sync(0xffffffffu, s, o);
            float inv = 1.0f / s;
            srow[lane] = v0 * inv;
            srow[lane + 32] = v1 * inv;
            srow[lane + 64] = v2 * inv;
            if (lane < 2) srow[lane + 96] = v3 * inv;
        }
    }
    __syncthreads();

    // ---- O = P V : 14x16 grid, 7x2 register tile ----
    {
        int i = tid >> 4, j = tid & 15;
        const float2* vs2 = (const float2*)vs;
        float acc[7][2];
        #pragma unroll
        for (int a = 0; a < 7; a++) { acc[a][0] = 0.0f; acc[a][1] = 0.0f; }
        for (int m = 0; m < NWIN; m++) {
            float2 vv = vs2[m * 16 + j];
            #pragma unroll
            for (int a = 0; a < 7; a++) {
                float pv = Ss[(i * 7 + a) * 99 + m];
                acc[a][0] += pv * vv.x;
                acc[a][1] += pv * vv.y;
            }
        }
        #pragma unroll
        for (int a = 0; a < 7; a++) {
            size_t o = ((size_t)b_ * NWIN + i * 7 + a) * CD + head * HD + j * 2;
            g_ao[o] = acc[a][0];
            g_ao[o + 1] = acc[a][1];
        }
    }
}

// ============ launch ============
extern "C" void kernel_launch(void* const* d_in, const int* in_sizes, int n_in,
                              void* d_out, int out_size) {
    const float* x     = (const float*)d_in[0];
    const float* mask  = (const float*)d_in[1];
    const float* n1w   = (const float*)d_in[2];
    const float* n1b   = (const float*)d_in[3];
    const float* qkvw  = (const float*)d_in[4];
    const float* qkvb  = (const float*)d_in[5];
    const float* relt  = (const float*)d_in[6];
    const float* projw = (const float*)d_in[7];
    const float* projb = (const float*)d_in[8];
    const float* fc1w  = (const float*)d_in[9];
    const float* fc1b  = (const float*)d_in[10];
    float* out = (float*)d_out;

    cudaFuncSetAttribute(attn_kernel, cudaFuncAttributeMaxDynamicSharedMemorySize, ATTN_SMEM);
    cudaFuncSetAttribute(gemm_tc<0>, cudaFuncAttributeMaxDynamicSharedMemorySize, GEMM_SMEM);
    cudaFuncSetAttribute(gemm_tc<1>, cudaFuncAttributeMaxDynamicSharedMemorySize, GEMM_SMEM);
    cudaFuncSetAttribute(gemm_tc<2>, cudaFuncAttributeMaxDynamicSharedMemorySize, GEMM_SMEM);

    bias_kernel<<<(NH * NWIN * NWIN + 1023) / 1024, 1024>>>(relt);
    ln_part_kernel<<<MTOT / 4, 128>>>(x, n1w, n1b);
    gemm_tc<0><<<dim3(MTOT / 128, 3), 256, GEMM_SMEM>>>(qkvw, qkvb, nullptr, nullptr);
    attn_kernel<<<dim3(BTOT, NH), 224, ATTN_SMEM>>>(mask);
    gemm_tc<1><<<dim3(MTOT / 128, 1), 256, GEMM_SMEM>>>(projw, projb, nullptr, nullptr);
    gemm_tc<2><<<dim3(MTOT / 128, 1), 256, GEMM_SMEM>>>(fc1w, fc1b, x, out);
}

// round 3
// speedup vs baseline: 2.5575x; 1.2367x over previous
#include <cuda_runtime.h>
#include <math.h>
#include <stdint.h>

// ---- problem constants ----
#define NWIN 98
#define NH 3
#define HD 32
#define CD 96
#define DD 16
#define HH 112
#define WW2 112
#define NWX 2048
#define BATCH 2
#define BTOT (BATCH*NWX)      // 4096
#define MTOT (BTOT*NWIN)      // 401408
#define LTOT (DD*HH*WW2)      // 200704
#define SCALE 0.17677669529663689f

// ---- scratch ----
__device__ float g_xw[(size_t)MTOT*CD];
__device__ float g_q[(size_t)BTOT*NH*NWIN*HD];
__device__ float g_k[(size_t)BTOT*NH*NWIN*HD];
__device__ float g_v[(size_t)BTOT*NH*NWIN*HD];
__device__ float g_ao[(size_t)MTOT*CD];
__device__ float g_y[(size_t)MTOT*CD];
__device__ float g_bias[NH*NWIN*NWIN];

// ---- tf32 helpers ----
__device__ __forceinline__ unsigned f2tf(float x) {
    unsigned r;
    asm("cvt.rna.tf32.f32 %0, %1;" : "=r"(r) : "f"(x));
    return r;
}
__device__ __forceinline__ void mma_tf32(float* d, uint4 a, uint2 b) {
    asm volatile(
        "mma.sync.aligned.m16n8k8.row.col.f32.tf32.tf32.f32 "
        "{%0,%1,%2,%3}, {%4,%5,%6,%7}, {%8,%9}, {%0,%1,%2,%3};"
        : "+f"(d[0]), "+f"(d[1]), "+f"(d[2]), "+f"(d[3])
        : "r"(a.x), "r"(a.y), "r"(a.z), "r"(a.w), "r"(b.x), "r"(b.y));
}

// ============ K0: rel-pos bias ============
__global__ void bias_kernel(const float* __restrict__ table) {
    int idx = blockIdx.x * blockDim.x + threadIdx.x;
    if (idx >= NH * NWIN * NWIN) return;
    int head = idx / (NWIN * NWIN);
    int r = idx % (NWIN * NWIN);
    int n = r / NWIN, m = r % NWIN;
    int d1 = n / 49, h1 = (n % 49) / 7, w1 = n % 7;
    int d2 = m / 49, h2 = (m % 49) / 7, w2 = m % 7;
    int t = (d1 - d2 + 1) * 169 + (h1 - h2 + 6) * 13 + (w1 - w2 + 6);
    g_bias[idx] = table[t * NH + head];
}

// ============ K1: LayerNorm + shift + window partition ============
__global__ void ln_part_kernel(const float* __restrict__ x,
                               const float* __restrict__ nw,
                               const float* __restrict__ nb) {
    int warp = (blockIdx.x * blockDim.x + threadIdx.x) >> 5;
    int lane = threadIdx.x & 31;
    if (warp >= MTOT) return;
    int b_ = warp / NWIN, n = warp % NWIN;
    int b = b_ >> 11;
    int widx = b_ & (NWX - 1);
    int wd = widx >> 8, wh = (widx >> 4) & 15, ww = widx & 15;
    int nd = n / 49, nr = n % 49, nh2 = nr / 7, nw2 = nr % 7;
    int dp = wd * 2 + nd, hp = wh * 7 + nh2, wp = ww * 7 + nw2;
    int d = dp + 1; if (d >= DD) d -= DD;
    int h = hp + 3; if (h >= HH) h -= HH;
    int w = wp + 3; if (w >= WW2) w -= WW2;
    size_t src = ((size_t)b * LTOT + (size_t)(d * (HH * WW2) + h * WW2 + w)) * CD;
    float v0 = x[src + lane], v1 = x[src + 32 + lane], v2 = x[src + 64 + lane];
    float s = v0 + v1 + v2;
    float ss = v0 * v0 + v1 * v1 + v2 * v2;
    #pragma unroll
    for (int o = 16; o; o >>= 1) {
        s  += __shfl_xor_sync(0xffffffffu, s, o);
        ss += __shfl_xor_sync(0xffffffffu, ss, o);
    }
    float mean = s * (1.0f / 96.0f);
    float var = ss * (1.0f / 96.0f) - mean * mean;
    float rs = rsqrtf(var + 1e-5f);
    size_t dst = (size_t)warp * CD;
    g_xw[dst + lane]      = (v0 - mean) * rs * nw[lane]      + nb[lane];
    g_xw[dst + 32 + lane] = (v1 - mean) * rs * nw[lane + 32] + nb[lane + 32];
    g_xw[dst + 64 + lane] = (v2 - mean) * rs * nw[lane + 64] + nb[lane + 64];
}

// ============ shared GEMM pieces ============
#define GEMM_SMEM (49152 + 36864)

__device__ __forceinline__ void gemm_packA(unsigned* sA, const float* A, int rowbase, int tid) {
    const float4* A4 = (const float4*)(A + (size_t)rowbase * 96);
    #pragma unroll
    for (int it = 0; it < 12; it++) {
        int idx = tid + it * 256;
        int r = idx / 24, k4 = idx % 24;
        float4 v = A4[r * 24 + k4];
        int mtile = r >> 4, mloc = r & 15;
        int gg = mloc & 7;
        int kbase = k4 * 4;
        int kt = kbase >> 3;
        int slotbase = ((kbase & 4) ? 2 : 0) | (mloc >> 3);
        unsigned* dst = sA + ((mtile * 12 + kt) * 32) * 4 + slotbase;
        dst[(gg * 4 + 0) * 4] = f2tf(v.x);
        dst[(gg * 4 + 1) * 4] = f2tf(v.y);
        dst[(gg * 4 + 2) * 4] = f2tf(v.z);
        dst[(gg * 4 + 3) * 4] = f2tf(v.w);
    }
}
__device__ __forceinline__ void gemm_packB(unsigned* sB, const float* Wt, int p, int tid) {
    const float4* B4 = (const float4*)(Wt + (size_t)p * 96 * 96);
    #pragma unroll
    for (int it = 0; it < 9; it++) {
        int idx = tid + it * 256;
        int c = idx / 24, k4 = idx % 24;
        float4 v = B4[c * 24 + k4];
        int nt = c >> 3, gg = c & 7;
        int kbase = k4 * 4;
        int kt = kbase >> 3;
        int slot = (kbase & 4) ? 1 : 0;
        unsigned* dst = sB + ((nt * 12 + kt) * 32) * 2 + slot;
        dst[(gg * 4 + 0) * 2] = f2tf(v.x);
        dst[(gg * 4 + 1) * 2] = f2tf(v.y);
        dst[(gg * 4 + 2) * 2] = f2tf(v.z);
        dst[(gg * 4 + 3) * 2] = f2tf(v.w);
    }
}
__device__ __forceinline__ void gemm_mma(float d[12][4], const unsigned* sA,
                                         const unsigned* sB, int w, int lane) {
    const uint4* a4 = (const uint4*)sA;
    const uint2* b2 = (const uint2*)sB;
    #pragma unroll
    for (int kt = 0; kt < 12; kt++) {
        uint4 af = a4[(w * 12 + kt) * 32 + lane];
        #pragma unroll
        for (int nt = 0; nt < 12; nt++) {
            uint2 bf = b2[(nt * 12 + kt) * 32 + lane];
            mma_tf32(d[nt], af, bf);
        }
    }
}

// ============ fused QKV GEMM: pack A once, loop 3 weight parts ============
__global__ __launch_bounds__(256, 2)
void gemm_qkv(const float* __restrict__ Wt, const float* __restrict__ bias) {
    extern __shared__ unsigned smu[];
    unsigned* sA = smu;
    unsigned* sB = smu + 12288;
    int rowbase = blockIdx.x * 128;
    int tid = threadIdx.x;
    int w = tid >> 5, lane = tid & 31;
    int g = lane >> 2, tig = lane & 3;

    gemm_packA(sA, g_xw, rowbase, tid);
    for (int p = 0; p < 3; p++) {
        if (p > 0) __syncthreads();
        gemm_packB(sB, Wt, p, tid);
        __syncthreads();
        float d[12][4];
        #pragma unroll
        for (int nt = 0; nt < 12; nt++)
            #pragma unroll
            for (int r = 0; r < 4; r++) d[nt][r] = 0.0f;
        gemm_mma(d, sA, sB, w, lane);
        #pragma unroll
        for (int nt = 0; nt < 12; nt++) {
            #pragma unroll
            for (int rr = 0; rr < 4; rr++) {
                int m = rowbase + w * 16 + g + ((rr >> 1) << 3);
                int c = nt * 8 + tig * 2 + (rr & 1);
                int b_ = m / NWIN, n = m % NWIN;
                float v = d[nt][rr] + bias[p * 96 + c];
                if (p == 0) v *= SCALE;
                int head = c >> 5, wd = c & 31;
                size_t dst = (((size_t)b_ * NH + head) * NWIN + n) * HD + wd;
                if (p == 0) g_q[dst] = v;
                else if (p == 1) g_k[dst] = v;
                else g_v[dst] = v;
            }
        }
    }
}

// ============ proj / fc1 GEMM ============
template<int EPI>
__global__ __launch_bounds__(256, 2)
void gemm_tc(const float* __restrict__ Wt,
             const float* __restrict__ bias,
             const float* __restrict__ resid,
             float* __restrict__ out) {
    extern __shared__ unsigned smu[];
    unsigned* sA = smu;
    unsigned* sB = smu + 12288;
    const float* A = (EPI == 1) ? g_ao : g_y;
    int rowbase = blockIdx.x * 128;
    int tid = threadIdx.x;
    int w = tid >> 5, lane = tid & 31;
    int g = lane >> 2, tig = lane & 3;

    gemm_packA(sA, A, rowbase, tid);
    gemm_packB(sB, Wt, 0, tid);
    __syncthreads();
    float d[12][4];
    #pragma unroll
    for (int nt = 0; nt < 12; nt++)
        #pragma unroll
        for (int r = 0; r < 4; r++) d[nt][r] = 0.0f;
    gemm_mma(d, sA, sB, w, lane);

    #pragma unroll
    for (int nt = 0; nt < 12; nt++) {
        #pragma unroll
        for (int rr = 0; rr < 4; rr++) {
            int m = rowbase + w * 16 + g + ((rr >> 1) << 3);
            int c = nt * 8 + tig * 2 + (rr & 1);
            int b_ = m / NWIN, n = m % NWIN;
            float v = d[nt][rr] + bias[c];
            if (EPI == 1) {
                int b = b_ >> 11;
                int widx = b_ & (NWX - 1);
                int wd = widx >> 8, wh = (widx >> 4) & 15, ww = widx & 15;
                int nd = n / 49, nr = n % 49, nh2 = nr / 7, nw2 = nr % 7;
                int dp = wd * 2 + nd, hp = wh * 7 + nh2, wp = ww * 7 + nw2;
                int dd = dp + 1; if (dd >= DD) dd -= DD;
                int hh = hp + 3; if (hh >= HH) hh -= HH;
                int ww3 = wp + 3; if (ww3 >= WW2) ww3 -= WW2;
                size_t dst = ((size_t)b * LTOT +
                              (size_t)(dd * (HH * WW2) + hh * WW2 + ww3)) * CD + c;
                g_y[dst] = v;
            } else {
                float ge = 0.5f * v * (1.0f + erff(v * 0.70710678118654752f));
                size_t o = (size_t)m * CD + c;
                out[o] = resid[o] + ge;
            }
        }
    }
}

// ============ K3: tensor-core window attention ============
// Per block: one (window, head). 224 threads = 7 warps, warp w owns m-tile w.
// smem: region0 = max(qA 14336 + kB 13312, Ss 112*104*4=46592) = 46592B
//       vB = 13312B  → total 59904B, 3 CTAs/SM.
#define ATTN_SMEM 59904
__global__ __launch_bounds__(224, 3)
void attn_kernel(const float* __restrict__ mask) {
    extern __shared__ unsigned smu[];
    unsigned* qA = smu;               // [7 mt][4 kt][32][4] u32
    unsigned* kB = smu + 3584;        // [13 nt][4 kt][32][2] u32
    float* Ss = (float*)smu;          // [112][104] overlaps qA/kB (phase 2+)
    unsigned* vB = smu + 11648;       // [4 nt][13 kt][32][2] u32

    int b_ = blockIdx.x;
    int head = blockIdx.y;
    int tid = threadIdx.x;
    int w = tid >> 5, lane = tid & 31;
    int g = lane >> 2, tig = lane & 3;
    size_t base = ((size_t)b_ * NH + head) * (size_t)(NWIN * HD);

    // ---- load + pack q/k/v into MMA fragments (tokens 98..103 zero-padded) ----
    {
        const float4* q4 = (const float4*)(g_q + base);
        const float4* k4 = (const float4*)(g_k + base);
        const float4* v4 = (const float4*)(g_v + base);
        for (int i4 = tid; i4 < 832; i4 += 224) {
            int n = i4 >> 3;
            int c = (i4 & 7) * 4;
            float4 qv, kv, vv;
            if (n < 98) { qv = q4[i4]; kv = k4[i4]; vv = v4[i4]; }
            else { qv = kv = vv = make_float4(0.f, 0.f, 0.f, 0.f); }
            // qA (A-frag: rows=tokens, k=dims)
            int mt = n >> 4, mloc = n & 15, gg = mloc & 7;
            unsigned* ad = qA + (mt * 4 + (c >> 3)) * 128 + gg * 16 + (((c & 4) ? 2 : 0) | (mloc >> 3));
            ad[0] = f2tf(qv.x); ad[4] = f2tf(qv.y); ad[8] = f2tf(qv.z); ad[12] = f2tf(qv.w);
            // kB (B-frag col-major: n=tokens, k=dims)
            int nt8 = n >> 3, g8 = n & 7;
            unsigned* bd = kB + (nt8 * 4 + (c >> 3)) * 64 + g8 * 8 + ((c & 4) ? 1 : 0);
            bd[0] = f2tf(kv.x); bd[2] = f2tf(kv.y); bd[4] = f2tf(kv.z); bd[6] = f2tf(kv.w);
            // vB (B-frag: n=dims(32), k=tokens)
            unsigned* vd = vB + ((c >> 3) * 13 + (n >> 3)) * 64 + (n & 3) * 2 + ((n & 4) ? 1 : 0);
            vd[((c & 7) + 0) * 8] = f2tf(vv.x);
            vd[((c & 7) + 1) * 8] = f2tf(vv.y);
            vd[((c & 7) + 2) * 8] = f2tf(vv.z);
            vd[((c & 7) + 3) * 8] = f2tf(vv.w);
        }
    }
    __syncthreads();

    // ---- S = Q K^T : warp w -> m-tile w, 13 n-tiles, 4 k-tiles ----
    float d[13][4];
    #pragma unroll
    for (int nt = 0; nt < 13; nt++)
        #pragma unroll
        for (int r = 0; r < 4; r++) d[nt][r] = 0.0f;
    {
        const uint4* a4 = (const uint4*)qA;
        const uint2* b2 = (const uint2*)kB;
        #pragma unroll
        for (int kt = 0; kt < 4; kt++) {
            uint4 af = a4[(w * 4 + kt) * 32 + lane];
            #pragma unroll
            for (int nt = 0; nt < 13; nt++) {
                uint2 bf = b2[(nt * 4 + kt) * 32 + lane];
                mma_tf32(d[nt], af, bf);
            }
        }
    }
    __syncthreads();   // all frag reads done; region0 now becomes Ss

    // ---- write S (+bias +mask), pad cols zeroed ----
    {
        int wm = b_ & (NWX - 1);
        const float* bb = g_bias + head * (NWIN * NWIN);
        const float* mm = mask + (size_t)wm * (NWIN * NWIN);
        #pragma unroll
        for (int nt = 0; nt < 13; nt++) {
            #pragma unroll
            for (int rr = 0; rr < 4; rr++) {
                int row = w * 16 + g + ((rr >> 1) << 3);
                int col = nt * 8 + tig * 2 + (rr & 1);
                if (row < 98) {
                    float v = 0.0f;
                    if (col < 98)
                        v = d[nt][rr] + __ldg(bb + row * 98 + col) + __ldg(mm + row * 98 + col);
                    Ss[row * 104 + col] = v;
                }
            }
        }
    }
    __syncthreads();

    // ---- softmax: 7 warps x 14 rows ----
    {
        for (int rr = 0; rr < 14; rr++) {
            int row = w * 14 + rr;
            float* srow = Ss + row * 104;
            float v0 = srow[lane];
            float v1 = srow[lane + 32];
            float v2 = srow[lane + 64];
            float v3 = (lane < 2) ? srow[lane + 96] : -1e30f;
            float mx = fmaxf(fmaxf(v0, v1), fmaxf(v2, v3));
            #pragma unroll
            for (int o = 16; o; o >>= 1) mx = fmaxf(mx, __shfl_xor_sync(0xffffffffu, mx, o));
            v0 = __expf(v0 - mx);
            v1 = __expf(v1 - mx);
            v2 = __expf(v2 - mx);
            v3 = (lane < 2) ? __expf(v3 - mx) : 0.0f;
            float s = v0 + v1 + v2 + v3;
            #pragma unroll
            for (int o = 16; o; o >>= 1) s += __shfl_xor_sync(0xffffffffu, s, o);
            float inv = 1.0f / s;
            srow[lane] = v0 * inv;
            srow[lane + 32] = v1 * inv;
            srow[lane + 64] = v2 * inv;
            if (lane < 2) srow[lane + 96] = v3 * inv;
        }
    }
    __syncthreads();

    // ---- O = P V : warp w -> m-tile w, 4 n-tiles, 13 k-tiles ----
    {
        float o[4][4];
        #pragma unroll
        for (int nt = 0; nt < 4; nt++)
            #pragma unroll
            for (int r = 0; r < 4; r++) o[nt][r] = 0.0f;
        const uint2* vb2 = (const uint2*)vB;
        int row0 = w * 16 + g;
        #pragma unroll
        for (int kt = 0; kt < 13; kt++) {
            uint4 af;
            af.x = f2tf(Ss[row0 * 104 + kt * 8 + tig]);
            af.y = f2tf(Ss[(row0 + 8) * 104 + kt * 8 + tig]);
            af.z = f2tf(Ss[row0 * 104 + kt * 8 + tig + 4]);
            af.w = f2tf(Ss[(row0 + 8) * 104 + kt * 8 + tig + 4]);
            #pragma unroll
            for (int nt = 0; nt < 4; nt++) {
                uint2 bf = vb2[(nt * 13 + kt) * 32 + lane];
                mma_tf32(o[nt], af, bf);
            }
        }
        #pragma unroll
        for (int nt = 0; nt < 4; nt++) {
            #pragma unroll
            for (int rr = 0; rr < 4; rr++) {
                int row = w * 16 + g + ((rr >> 1) << 3);
                int col = nt * 8 + tig * 2 + (rr & 1);
                if (row < 98)
                    g_ao[((size_t)b_ * NWIN + row) * CD + head * HD + col] = o[nt][rr];
            }
        }
    }
}

// ============ launch ============
extern "C" void kernel_launch(void* const* d_in, const int* in_sizes, int n_in,
                              void* d_out, int out_size) {
    const float* x     = (const float*)d_in[0];
    const float* mask  = (const float*)d_in[1];
    const float* n1w   = (const float*)d_in[2];
    const float* n1b   = (const float*)d_in[3];
    const float* qkvw  = (const float*)d_in[4];
    const float* qkvb  = (const float*)d_in[5];
    const float* relt  = (const float*)d_in[6];
    const float* projw = (const float*)d_in[7];
    const float* projb = (const float*)d_in[8];
    const float* fc1w  = (const float*)d_in[9];
    const float* fc1b  = (const float*)d_in[10];
    float* out = (float*)d_out;

    cudaFuncSetAttribute(attn_kernel, cudaFuncAttributeMaxDynamicSharedMemorySize, ATTN_SMEM);
    cudaFuncSetAttribute(gemm_qkv, cudaFuncAttributeMaxDynamicSharedMemorySize, GEMM_SMEM);
    cudaFuncSetAttribute(gemm_tc<1>, cudaFuncAttributeMaxDynamicSharedMemorySize, GEMM_SMEM);
    cudaFuncSetAttribute(gemm_tc<2>, cudaFuncAttributeMaxDynamicSharedMemorySize, GEMM_SMEM);

    bias_kernel<<<(NH * NWIN * NWIN + 1023) / 1024, 1024>>>(relt);
    ln_part_kernel<<<MTOT / 4, 128>>>(x, n1w, n1b);
    gemm_qkv<<<MTOT / 128, 256, GEMM_SMEM>>>(qkvw, qkvb);
    attn_kernel<<<dim3(BTOT, NH), 224, ATTN_SMEM>>>(mask);
    gemm_tc<1><<<MTOT / 128, 256, GEMM_SMEM>>>(projw, projb, nullptr, nullptr);
    gemm_tc<2><<<MTOT / 128, 256, GEMM_SMEM>>>(fc1w, fc1b, x, out);
}

// round 4
// speedup vs baseline: 3.6022x; 1.4085x over previous
#include <cuda_runtime.h>
#include <math.h>
#include <stdint.h>

// ---- problem constants ----
#define NWIN 98
#define NH 3
#define HD 32
#define CD 96
#define DD 16
#define HH 112
#define WW2 112
#define NWX 2048
#define BATCH 2
#define BTOT (BATCH*NWX)      // 4096
#define MTOT (BTOT*NWIN)      // 401408
#define LTOT (DD*HH*WW2)      // 200704
#define SCALE 0.17677669529663689f

// ---- scratch ----
__device__ float g_xw[(size_t)MTOT*CD];
__device__ float g_q[(size_t)BTOT*NH*NWIN*HD];
__device__ float g_k[(size_t)BTOT*NH*NWIN*HD];
__device__ float g_v[(size_t)BTOT*NH*NWIN*HD];
__device__ float g_ao[(size_t)MTOT*CD];
__device__ float g_y[(size_t)MTOT*CD];
__device__ float g_bm[8*NH*NWIN*NWIN];   // bias+mask per (class, head)

// ---- tf32 helpers ----
__device__ __forceinline__ unsigned f2tf(float x) {
    unsigned r;
    asm("cvt.rna.tf32.f32 %0, %1;" : "=r"(r) : "f"(x));
    return r;
}
__device__ __forceinline__ void mma_tf32(float* d, uint4 a, uint2 b) {
    asm volatile(
        "mma.sync.aligned.m16n8k8.row.col.f32.tf32.tf32.f32 "
        "{%0,%1,%2,%3}, {%4,%5,%6,%7}, {%8,%9}, {%0,%1,%2,%3};"
        : "+f"(d[0]), "+f"(d[1]), "+f"(d[2]), "+f"(d[3])
        : "r"(a.x), "r"(a.y), "r"(a.z), "r"(a.w), "r"(b.x), "r"(b.y));
}

// ============ K0: combined bias+mask table, 8 window classes x 3 heads ============
__global__ void bm_kernel(const float* __restrict__ table,
                          const float* __restrict__ mask) {
    int idx = blockIdx.x * blockDim.x + threadIdx.x;
    if (idx >= 8 * NH * NWIN * NWIN) return;
    int cls = idx / (NH * NWIN * NWIN);
    int rem = idx % (NH * NWIN * NWIN);
    int head = rem / (NWIN * NWIN);
    int r = rem % (NWIN * NWIN);
    int n = r / NWIN, m = r % NWIN;
    // rel-pos bias
    int d1 = n / 49, h1 = (n % 49) / 7, w1 = n % 7;
    int d2 = m / 49, h2 = (m % 49) / 7, w2 = m % 7;
    int t = (d1 - d2 + 1) * 169 + (h1 - h2 + 6) * 13 + (w1 - w2 + 6);
    // representative window for class
    int wd = (cls & 4) ? 7 : 0;
    int wh = (cls & 2) ? 15 : 0;
    int ww = (cls & 1) ? 15 : 0;
    int widx = wd * 256 + wh * 16 + ww;
    g_bm[idx] = table[t * NH + head] + mask[(size_t)widx * (NWIN * NWIN) + r];
}

// ============ K1: LayerNorm + shift + window partition ============
__global__ void ln_part_kernel(const float* __restrict__ x,
                               const float* __restrict__ nw,
                               const float* __restrict__ nb) {
    int warp = (blockIdx.x * blockDim.x + threadIdx.x) >> 5;
    int lane = threadIdx.x & 31;
    if (warp >= MTOT) return;
    int b_ = warp / NWIN, n = warp % NWIN;
    int b = b_ >> 11;
    int widx = b_ & (NWX - 1);
    int wd = widx >> 8, wh = (widx >> 4) & 15, ww = widx & 15;
    int nd = n / 49, nr = n % 49, nh2 = nr / 7, nw2 = nr % 7;
    int dp = wd * 2 + nd, hp = wh * 7 + nh2, wp = ww * 7 + nw2;
    int d = dp + 1; if (d >= DD) d -= DD;
    int h = hp + 3; if (h >= HH) h -= HH;
    int w = wp + 3; if (w >= WW2) w -= WW2;
    size_t src = ((size_t)b * LTOT + (size_t)(d * (HH * WW2) + h * WW2 + w)) * CD;
    float v0 = x[src + lane], v1 = x[src + 32 + lane], v2 = x[src + 64 + lane];
    float s = v0 + v1 + v2;
    float ss = v0 * v0 + v1 * v1 + v2 * v2;
    #pragma unroll
    for (int o = 16; o; o >>= 1) {
        s  += __shfl_xor_sync(0xffffffffu, s, o);
        ss += __shfl_xor_sync(0xffffffffu, ss, o);
    }
    float mean = s * (1.0f / 96.0f);
    float var = ss * (1.0f / 96.0f) - mean * mean;
    float rs = rsqrtf(var + 1e-5f);
    size_t dst = (size_t)warp * CD;
    g_xw[dst + lane]      = (v0 - mean) * rs * nw[lane]      + nb[lane];
    g_xw[dst + 32 + lane] = (v1 - mean) * rs * nw[lane + 32] + nb[lane + 32];
    g_xw[dst + 64 + lane] = (v2 - mean) * rs * nw[lane + 64] + nb[lane + 64];
}

// ============ shared GEMM pieces ============
#define GEMM_SMEM (49152 + 36864)

__device__ __forceinline__ void gemm_packA(unsigned* sA, const float* A, int rowbase, int tid) {
    const float4* A4 = (const float4*)(A + (size_t)rowbase * 96);
    #pragma unroll
    for (int it = 0; it < 12; it++) {
        int idx = tid + it * 256;
        int r = idx / 24, k4 = idx % 24;
        float4 v = A4[r * 24 + k4];
        int mtile = r >> 4, mloc = r & 15;
        int gg = mloc & 7;
        int kbase = k4 * 4;
        int kt = kbase >> 3;
        int slotbase = ((kbase & 4) ? 2 : 0) | (mloc >> 3);
        unsigned* dst = sA + ((mtile * 12 + kt) * 32) * 4 + slotbase;
        dst[(gg * 4 + 0) * 4] = f2tf(v.x);
        dst[(gg * 4 + 1) * 4] = f2tf(v.y);
        dst[(gg * 4 + 2) * 4] = f2tf(v.z);
        dst[(gg * 4 + 3) * 4] = f2tf(v.w);
    }
}
__device__ __forceinline__ void gemm_packB(unsigned* sB, const float* Wt, int p, int tid) {
    const float4* B4 = (const float4*)(Wt + (size_t)p * 96 * 96);
    #pragma unroll
    for (int it = 0; it < 9; it++) {
        int idx = tid + it * 256;
        int c = idx / 24, k4 = idx % 24;
        float4 v = B4[c * 24 + k4];
        int nt = c >> 3, gg = c & 7;
        int kbase = k4 * 4;
        int kt = kbase >> 3;
        int slot = (kbase & 4) ? 1 : 0;
        unsigned* dst = sB + ((nt * 12 + kt) * 32) * 2 + slot;
        dst[(gg * 4 + 0) * 2] = f2tf(v.x);
        dst[(gg * 4 + 1) * 2] = f2tf(v.y);
        dst[(gg * 4 + 2) * 2] = f2tf(v.z);
        dst[(gg * 4 + 3) * 2] = f2tf(v.w);
    }
}
__device__ __forceinline__ void gemm_mma(float d[12][4], const unsigned* sA,
                                         const unsigned* sB, int w, int lane) {
    const uint4* a4 = (const uint4*)sA;
    const uint2* b2 = (const uint2*)sB;
    #pragma unroll
    for (int kt = 0; kt < 12; kt++) {
        uint4 af = a4[(w * 12 + kt) * 32 + lane];
        #pragma unroll
        for (int nt = 0; nt < 12; nt++) {
            uint2 bf = b2[(nt * 12 + kt) * 32 + lane];
            mma_tf32(d[nt], af, bf);
        }
    }
}

// ============ fused QKV GEMM ============
__global__ __launch_bounds__(256, 2)
void gemm_qkv(const float* __restrict__ Wt, const float* __restrict__ bias) {
    extern __shared__ unsigned smu[];
    unsigned* sA = smu;
    unsigned* sB = smu + 12288;
    int rowbase = blockIdx.x * 128;
    int tid = threadIdx.x;
    int w = tid >> 5, lane = tid & 31;
    int g = lane >> 2, tig = lane & 3;

    gemm_packA(sA, g_xw, rowbase, tid);
    int m0 = rowbase + w * 16 + g;
    int b0 = m0 / NWIN, n0 = m0 % NWIN;
    int b1 = (m0 + 8) / NWIN, n1 = (m0 + 8) % NWIN;
    for (int p = 0; p < 3; p++) {
        if (p > 0) __syncthreads();
        gemm_packB(sB, Wt, p, tid);
        __syncthreads();
        float d[12][4];
        #pragma unroll
        for (int nt = 0; nt < 12; nt++)
            #pragma unroll
            for (int r = 0; r < 4; r++) d[nt][r] = 0.0f;
        gemm_mma(d, sA, sB, w, lane);
        float* dstbuf = (p == 0) ? g_q : (p == 1) ? g_k : g_v;
        float sc = (p == 0) ? SCALE : 1.0f;
        #pragma unroll
        for (int nt = 0; nt < 12; nt++) {
            int c = nt * 8 + tig * 2;
            int head = c >> 5, wd = c & 31;
            float bx = bias[p * 96 + c], by = bias[p * 96 + c + 1];
            float2 v0 = make_float2((d[nt][0] + bx) * sc, (d[nt][1] + by) * sc);
            float2 v1 = make_float2((d[nt][2] + bx) * sc, (d[nt][3] + by) * sc);
            *(float2*)(dstbuf + ((((size_t)b0 * NH + head) * NWIN + n0) * HD + wd)) = v0;
            *(float2*)(dstbuf + ((((size_t)b1 * NH + head) * NWIN + n1) * HD + wd)) = v1;
        }
    }
}

// ============ proj / fc1 GEMM ============
template<int EPI>
__global__ __launch_bounds__(256, 2)
void gemm_tc(const float* __restrict__ Wt,
             const float* __restrict__ bias,
             const float* __restrict__ resid,
             float* __restrict__ out) {
    extern __shared__ unsigned smu[];
    unsigned* sA = smu;
    unsigned* sB = smu + 12288;
    const float* A = (EPI == 1) ? g_ao : g_y;
    int rowbase = blockIdx.x * 128;
    int tid = threadIdx.x;
    int w = tid >> 5, lane = tid & 31;
    int g = lane >> 2, tig = lane & 3;

    gemm_packA(sA, A, rowbase, tid);
    gemm_packB(sB, Wt, 0, tid);
    __syncthreads();
    float d[12][4];
    #pragma unroll
    for (int nt = 0; nt < 12; nt++)
        #pragma unroll
        for (int r = 0; r < 4; r++) d[nt][r] = 0.0f;
    gemm_mma(d, sA, sB, w, lane);

    if (EPI == 1) {
        // hoisted spatial scatter per row
        size_t rowdst[2];
        #pragma unroll
        for (int rr = 0; rr < 2; rr++) {
            int m = rowbase + w * 16 + g + rr * 8;
            int b_ = m / NWIN, n = m % NWIN;
            int b = b_ >> 11;
            int widx = b_ & (NWX - 1);
            int wd = widx >> 8, wh = (widx >> 4) & 15, ww = widx & 15;
            int nd = n / 49, nr = n % 49, nh2 = nr / 7, nw2 = nr % 7;
            int dp = wd * 2 + nd, hp = wh * 7 + nh2, wp = ww * 7 + nw2;
            int dd = dp + 1; if (dd >= DD) dd -= DD;
            int hh = hp + 3; if (hh >= HH) hh -= HH;
            int ww3 = wp + 3; if (ww3 >= WW2) ww3 -= WW2;
            rowdst[rr] = ((size_t)b * LTOT +
                          (size_t)(dd * (HH * WW2) + hh * WW2 + ww3)) * CD;
        }
        #pragma unroll
        for (int nt = 0; nt < 12; nt++) {
            int c = nt * 8 + tig * 2;
            float bx = bias[c], by = bias[c + 1];
            *(float2*)(g_y + rowdst[0] + c) = make_float2(d[nt][0] + bx, d[nt][1] + by);
            *(float2*)(g_y + rowdst[1] + c) = make_float2(d[nt][2] + bx, d[nt][3] + by);
        }
    } else {
        int m0 = rowbase + w * 16 + g;
        #pragma unroll
        for (int nt = 0; nt < 12; nt++) {
            int c = nt * 8 + tig * 2;
            float bx = bias[c], by = bias[c + 1];
            #pragma unroll
            for (int rr = 0; rr < 2; rr++) {
                size_t o = (size_t)(m0 + rr * 8) * CD + c;
                float v0 = d[nt][rr * 2] + bx;
                float v1 = d[nt][rr * 2 + 1] + by;
                float g0 = 0.5f * v0 * (1.0f + erff(v0 * 0.70710678118654752f));
                float g1 = 0.5f * v1 * (1.0f + erff(v1 * 0.70710678118654752f));
                float2 rv = *(const float2*)(resid + o);
                *(float2*)(out + o) = make_float2(rv.x + g0, rv.y + g1);
            }
        }
    }
}

// ============ K3: tensor-core window attention (direct-LDS fragments) ============
// smem (u32 words):
//   q_u [112][36] = 4032   @ 0        (tf32 bits)
//   k_u [104][36] = 3744   @ 4032
//   Ss  [112][108] = 12096 @ 0   (float, overlaps q_u/k_u after S phase)
//   vT  [32][108]  = 3456  @ 12096    (tf32 bits, dims x tokens)
// total = 15552 words = 62208 B  -> 3 CTAs/SM
#define ATTN_SMEM 62208
__global__ __launch_bounds__(224, 3)
void attn_kernel() {
    extern __shared__ unsigned smu[];
    unsigned* q_u = smu;
    unsigned* k_u = smu + 4032;
    float* Ss = (float*)smu;
    unsigned* vT = smu + 12096;

    int b_ = blockIdx.x;
    int head = blockIdx.y;
    int tid = threadIdx.x;
    int w = tid >> 5, lane = tid & 31;
    int g = lane >> 2, tig = lane & 3;
    size_t base = ((size_t)b_ * NH + head) * (size_t)(NWIN * HD);

    // ---- coalesced load, tf32-convert, plain-layout store ----
    {
        const float4* q4 = (const float4*)(g_q + base);
        const float4* k4 = (const float4*)(g_k + base);
        const float4* v4 = (const float4*)(g_v + base);
        for (int i4 = tid; i4 < 832; i4 += 224) {
            int n = i4 >> 3;
            int c = (i4 & 7) << 2;
            if (n < 98) {
                float4 qv = q4[i4];
                float4 kv = k4[i4];
                float4 vv = v4[i4];
                uint4 qt = make_uint4(f2tf(qv.x), f2tf(qv.y), f2tf(qv.z), f2tf(qv.w));
                uint4 kt = make_uint4(f2tf(kv.x), f2tf(kv.y), f2tf(kv.z), f2tf(kv.w));
                *(uint4*)(q_u + n * 36 + c) = qt;
                *(uint4*)(k_u + n * 36 + c) = kt;
                vT[(c + 0) * 108 + n] = f2tf(vv.x);
                vT[(c + 1) * 108 + n] = f2tf(vv.y);
                vT[(c + 2) * 108 + n] = f2tf(vv.z);
                vT[(c + 3) * 108 + n] = f2tf(vv.w);
            } else {
                vT[(c + 0) * 108 + n] = 0u;
                vT[(c + 1) * 108 + n] = 0u;
                vT[(c + 2) * 108 + n] = 0u;
                vT[(c + 3) * 108 + n] = 0u;
            }
        }
    }
    __syncthreads();

    int r0 = w * 16 + g;
    // ---- S = Q K^T : direct LDS fragments, conflict-free ----
    float d[13][4];
    #pragma unroll
    for (int nt = 0; nt < 13; nt++)
        #pragma unroll
        for (int r = 0; r < 4; r++) d[nt][r] = 0.0f;
    {
        uint4 af[4];
        #pragma unroll
        for (int kt = 0; kt < 4; kt++) {
            af[kt].x = q_u[r0 * 36 + kt * 8 + tig];
            af[kt].y = q_u[(r0 + 8) * 36 + kt * 8 + tig];
            af[kt].z = q_u[r0 * 36 + kt * 8 + tig + 4];
            af[kt].w = q_u[(r0 + 8) * 36 + kt * 8 + tig + 4];
        }
        #pragma unroll
        for (int nt = 0; nt < 13; nt++) {
            #pragma unroll
            for (int kt = 0; kt < 4; kt++) {
                uint2 bf;
                bf.x = k_u[(nt * 8 + g) * 36 + kt * 8 + tig];
                bf.y = k_u[(nt * 8 + g) * 36 + kt * 8 + tig + 4];
                mma_tf32(d[nt], af[kt], bf);
            }
        }
    }
    __syncthreads();   // all q/k reads done; region becomes Ss

    // ---- in-register bias/mask add + exp + row-sum (no max: scores bounded) ----
    {
        int widx = b_ & (NWX - 1);
        int cls = (((widx >> 8) == 7) << 2) | ((((widx >> 4) & 15) == 15) << 1) |
                  ((widx & 15) == 15);
        const float* bmp = g_bm + (size_t)(cls * NH + head) * (NWIN * NWIN);
        bool v0 = r0 < 98, v1 = (r0 + 8) < 98;
        float s0 = 0.0f, s1 = 0.0f;
        #pragma unroll
        for (int nt = 0; nt < 13; nt++) {
            int c0 = nt * 8 + tig * 2;
            float e0 = 0.f, e1 = 0.f, e2 = 0.f, e3 = 0.f;
            if (c0 < 98) {
                if (v0) {
                    float2 bb = __ldg((const float2*)(bmp + r0 * 98 + c0));
                    e0 = __expf(d[nt][0] + bb.x);
                    e1 = __expf(d[nt][1] + bb.y);
                }
                if (v1) {
                    float2 bb = __ldg((const float2*)(bmp + (r0 + 8) * 98 + c0));
                    e2 = __expf(d[nt][2] + bb.x);
                    e3 = __expf(d[nt][3] + bb.y);
                }
            }
            d[nt][0] = e0; d[nt][1] = e1; d[nt][2] = e2; d[nt][3] = e3;
            s0 += e0 + e1; s1 += e2 + e3;
        }
        s0 += __shfl_xor_sync(0xffffffffu, s0, 1);
        s0 += __shfl_xor_sync(0xffffffffu, s0, 2);
        s1 += __shfl_xor_sync(0xffffffffu, s1, 1);
        s1 += __shfl_xor_sync(0xffffffffu, s1, 2);
        float i0 = v0 ? (1.0f / s0) : 0.0f;
        float i1 = v1 ? (1.0f / s1) : 0.0f;
        #pragma unroll
        for (int nt = 0; nt < 13; nt++) {
            int c0 = nt * 8 + tig * 2;   // <= 102 < 108
            if (v0) *(float2*)(Ss + r0 * 108 + c0) =
                make_float2(d[nt][0] * i0, d[nt][1] * i0);
            if (v1) *(float2*)(Ss + (r0 + 8) * 108 + c0) =
                make_float2(d[nt][2] * i1, d[nt][3] * i1);
        }
    }
    __syncthreads();

    // ---- O = P V ----
    {
        float o[4][4];
        #pragma unroll
        for (int nt = 0; nt < 4; nt++)
            #pragma unroll
            for (int r = 0; r < 4; r++) o[nt][r] = 0.0f;
        #pragma unroll
        for (int kt = 0; kt < 13; kt++) {
            uint4 af;
            af.x = f2tf(Ss[r0 * 108 + kt * 8 + tig]);
            af.y = f2tf(Ss[(r0 + 8) * 108 + kt * 8 + tig]);
            af.z = f2tf(Ss[r0 * 108 + kt * 8 + tig + 4]);
            af.w = f2tf(Ss[(r0 + 8) * 108 + kt * 8 + tig + 4]);
            #pragma unroll
            for (int nt = 0; nt < 4; nt++) {
                uint2 bf;
                bf.x = vT[(nt * 8 + g) * 108 + kt * 8 + tig];
                bf.y = vT[(nt * 8 + g) * 108 + kt * 8 + tig + 4];
                mma_tf32(o[nt], af, bf);
            }
        }
        #pragma unroll
        for (int nt = 0; nt < 4; nt++) {
            int c = nt * 8 + tig * 2;
            if (r0 < 98)
                *(float2*)(g_ao + ((size_t)b_ * NWIN + r0) * CD + head * HD + c) =
                    make_float2(o[nt][0], o[nt][1]);
            if (r0 + 8 < 98)
                *(float2*)(g_ao + ((size_t)b_ * NWIN + r0 + 8) * CD + head * HD + c) =
                    make_float2(o[nt][2], o[nt][3]);
        }
    }
}

// ============ launch ============
extern "C" void kernel_launch(void* const* d_in, const int* in_sizes, int n_in,
                              void* d_out, int out_size) {
    const float* x     = (const float*)d_in[0];
    const float* mask  = (const float*)d_in[1];
    const float* n1w   = (const float*)d_in[2];
    const float* n1b   = (const float*)d_in[3];
    const float* qkvw  = (const float*)d_in[4];
    const float* qkvb  = (const float*)d_in[5];
    const float* relt  = (const float*)d_in[6];
    const float* projw = (const float*)d_in[7];
    const float* projb = (const float*)d_in[8];
    const float* fc1w  = (const float*)d_in[9];
    const float* fc1b  = (const float*)d_in[10];
    float* out = (float*)d_out;

    cudaFuncSetAttribute(attn_kernel, cudaFuncAttributeMaxDynamicSharedMemorySize, ATTN_SMEM);
    cudaFuncSetAttribute(gemm_qkv, cudaFuncAttributeMaxDynamicSharedMemorySize, GEMM_SMEM);
    cudaFuncSetAttribute(gemm_tc<1>, cudaFuncAttributeMaxDynamicSharedMemorySize, GEMM_SMEM);
    cudaFuncSetAttribute(gemm_tc<2>, cudaFuncAttributeMaxDynamicSharedMemorySize, GEMM_SMEM);

    bm_kernel<<<(8 * NH * NWIN * NWIN + 255) / 256, 256>>>(relt, mask);
    ln_part_kernel<<<MTOT / 4, 128>>>(x, n1w, n1b);
    gemm_qkv<<<MTOT / 128, 256, GEMM_SMEM>>>(qkvw, qkvb);
    attn_kernel<<<dim3(BTOT, NH), 224, ATTN_SMEM>>>();
    gemm_tc<1><<<MTOT / 128, 256, GEMM_SMEM>>>(projw, projb, nullptr, nullptr);
    gemm_tc<2><<<MTOT / 128, 256, GEMM_SMEM>>>(fc1w, fc1b, x, out);
}

// round 5
// speedup vs baseline: 4.6052x; 1.2784x over previous
#include <cuda_runtime.h>
#include <math.h>
#include <stdint.h>

// ---- problem constants ----
#define NWIN 98
#define NH 3
#define HD 32
#define CD 96
#define DD 16
#define HH 112
#define WW2 112
#define NWX 2048
#define BATCH 2
#define BTOT (BATCH*NWX)      // 4096
#define MTOT (BTOT*NWIN)      // 401408
#define LTOT (DD*HH*WW2)      // 200704
#define SCALE 0.17677669529663689f

// ---- scratch ----
__device__ float g_q[(size_t)BTOT*NH*NWIN*HD];
__device__ float g_k[(size_t)BTOT*NH*NWIN*HD];
__device__ float g_v[(size_t)BTOT*NH*NWIN*HD];
__device__ float g_ao[(size_t)MTOT*CD];
__device__ float g_y[(size_t)MTOT*CD];
__device__ float g_bm[8*NH*NWIN*NWIN];   // bias+mask per (class, head)
__device__ unsigned g_Bp[5*9216];        // prepacked B frags: qkv0,1,2, proj, fc1

// ---- tf32 helpers ----
__device__ __forceinline__ unsigned f2tf(float x) {
    unsigned r;
    asm("cvt.rna.tf32.f32 %0, %1;" : "=r"(r) : "f"(x));
    return r;
}
__device__ __forceinline__ void mma_tf32(float* d, uint4 a, uint2 b) {
    asm volatile(
        "mma.sync.aligned.m16n8k8.row.col.f32.tf32.tf32.f32 "
        "{%0,%1,%2,%3}, {%4,%5,%6,%7}, {%8,%9}, {%0,%1,%2,%3};"
        : "+f"(d[0]), "+f"(d[1]), "+f"(d[2]), "+f"(d[3])
        : "r"(a.x), "r"(a.y), "r"(a.z), "r"(a.w), "r"(b.x), "r"(b.y));
}

// ============ K0a: combined bias+mask table, 8 window classes x 3 heads ============
__global__ void bm_kernel(const float* __restrict__ table,
                          const float* __restrict__ mask) {
    int idx = blockIdx.x * blockDim.x + threadIdx.x;
    if (idx >= 8 * NH * NWIN * NWIN) return;
    int cls = idx / (NH * NWIN * NWIN);
    int rem = idx % (NH * NWIN * NWIN);
    int head = rem / (NWIN * NWIN);
    int r = rem % (NWIN * NWIN);
    int n = r / NWIN, m = r % NWIN;
    int d1 = n / 49, h1 = (n % 49) / 7, w1 = n % 7;
    int d2 = m / 49, h2 = (m % 49) / 7, w2 = m % 7;
    int t = (d1 - d2 + 1) * 169 + (h1 - h2 + 6) * 13 + (w1 - w2 + 6);
    int wd = (cls & 4) ? 7 : 0;
    int wh = (cls & 2) ? 15 : 0;
    int ww = (cls & 1) ? 15 : 0;
    int widx = wd * 256 + wh * 16 + ww;
    g_bm[idx] = table[t * NH + head] + mask[(size_t)widx * (NWIN * NWIN) + r];
}

// ============ K0b: prepack weight matrices into MMA B-fragment layout ============
__global__ void prepack_kernel(const float* __restrict__ qkvw,
                               const float* __restrict__ projw,
                               const float* __restrict__ fc1w) {
    int idx = blockIdx.x * blockDim.x + threadIdx.x;
    if (idx >= 5 * 9216) return;
    int mat = idx / 9216, rem = idx % 9216;
    int c = rem / 96, k = rem % 96;
    float v;
    if (mat < 3) v = qkvw[(size_t)(mat * 96 + c) * 96 + k];
    else if (mat == 3) v = projw[(size_t)c * 96 + k];
    else v = fc1w[(size_t)c * 96 + k];
    int word = (((c >> 3) * 12 + (k >> 3)) * 32 + (c & 7) * 4 + (k & 3)) * 2 + ((k >> 2) & 1);
    g_Bp[mat * 9216 + word] = f2tf(v);
}

// ============ GEMM common ============
#define GEMM_SMEM ((12800 + 9216) * 4)

__device__ __forceinline__ void mma12(float d[12][4], const unsigned* sAu,
                                      const unsigned* sB, int r0, int tig, int lane) {
    const uint2* b2 = (const uint2*)sB;
    #pragma unroll
    for (int kt = 0; kt < 12; kt++) {
        uint4 af;
        af.x = sAu[r0 * 100 + kt * 8 + tig];
        af.y = sAu[(r0 + 8) * 100 + kt * 8 + tig];
        af.z = sAu[r0 * 100 + kt * 8 + tig + 4];
        af.w = sAu[(r0 + 8) * 100 + kt * 8 + tig + 4];
        #pragma unroll
        for (int nt = 0; nt < 12; nt++) {
            uint2 bf = b2[(nt * 12 + kt) * 32 + lane];
            mma_tf32(d[nt], af, bf);
        }
    }
}

// ============ K1: fused LayerNorm + window-partition + QKV GEMM ============
__global__ __launch_bounds__(256, 2)
void gemm_qkv(const float* __restrict__ x,
              const float* __restrict__ nw,
              const float* __restrict__ nb,
              const float* __restrict__ bias) {
    extern __shared__ unsigned smu[];
    unsigned* sAu = smu;          // [128][100] tf32 bits
    unsigned* sB  = smu + 12800;  // 9216 words
    int rowbase = blockIdx.x * 128;
    int tid = threadIdx.x;
    int w = tid >> 5, lane = tid & 31;
    int g = lane >> 2, tig = lane & 3;

    float nw0 = nw[lane], nw1 = nw[lane + 32], nw2 = nw[lane + 64];
    float nb0 = nb[lane], nb1 = nb[lane + 32], nb2 = nb[lane + 64];

    // ---- phase A: gather (shift+window) + LayerNorm -> sAu ----
    for (int i = 0; i < 16; i++) {
        int r = w * 16 + i;
        int m = rowbase + r;
        int b_ = m / NWIN, n = m % NWIN;
        int b = b_ >> 11;
        int widx = b_ & (NWX - 1);
        int wd = widx >> 8, wh = (widx >> 4) & 15, ww = widx & 15;
        int nd = n / 49, nr = n % 49, nh2 = nr / 7, nw2i = nr % 7;
        int dp = wd * 2 + nd, hp = wh * 7 + nh2, wp = ww * 7 + nw2i;
        int d = dp + 1; if (d >= DD) d -= DD;
        int h = hp + 3; if (h >= HH) h -= HH;
        int wq = wp + 3; if (wq >= WW2) wq -= WW2;
        size_t src = ((size_t)b * LTOT + (size_t)(d * (HH * WW2) + h * WW2 + wq)) * CD;
        float v0 = x[src + lane], v1 = x[src + 32 + lane], v2 = x[src + 64 + lane];
        float s = v0 + v1 + v2;
        float ss = v0 * v0 + v1 * v1 + v2 * v2;
        #pragma unroll
        for (int o = 16; o; o >>= 1) {
            s  += __shfl_xor_sync(0xffffffffu, s, o);
            ss += __shfl_xor_sync(0xffffffffu, ss, o);
        }
        float mean = s * (1.0f / 96.0f);
        float var = ss * (1.0f / 96.0f) - mean * mean;
        float rs = rsqrtf(var + 1e-5f);
        sAu[r * 100 + lane]      = f2tf((v0 - mean) * rs * nw0 + nb0);
        sAu[r * 100 + lane + 32] = f2tf((v1 - mean) * rs * nw1 + nb1);
        sAu[r * 100 + lane + 64] = f2tf((v2 - mean) * rs * nw2 + nb2);
    }

    int m0 = rowbase + w * 16 + g;
    int b0 = m0 / NWIN, n0 = m0 % NWIN;
    int b1 = (m0 + 8) / NWIN, n1 = (m0 + 8) % NWIN;
    int r0 = w * 16 + g;
    __syncthreads();

    // ---- phase B: loop q/k/v weight parts ----
    for (int p = 0; p < 3; p++) {
        if (p > 0) __syncthreads();
        {
            const uint4* s4 = (const uint4*)(g_Bp + p * 9216);
            uint4* d4 = (uint4*)sB;
            #pragma unroll
            for (int i = 0; i < 9; i++) d4[tid + i * 256] = s4[tid + i * 256];
        }
        __syncthreads();
        float d[12][4];
        #pragma unroll
        for (int nt = 0; nt < 12; nt++)
            #pragma unroll
            for (int r = 0; r < 4; r++) d[nt][r] = 0.0f;
        mma12(d, sAu, sB, r0, tig, lane);

        float* dstbuf = (p == 0) ? g_q : (p == 1) ? g_k : g_v;
        float sc = (p == 0) ? SCALE : 1.0f;
        #pragma unroll
        for (int nt = 0; nt < 12; nt++) {
            int c = nt * 8 + tig * 2;
            int head = c >> 5, wd = c & 31;
            float bx = bias[p * 96 + c], by = bias[p * 96 + c + 1];
            float2 v0 = make_float2((d[nt][0] + bx) * sc, (d[nt][1] + by) * sc);
            float2 v1 = make_float2((d[nt][2] + bx) * sc, (d[nt][3] + by) * sc);
            *(float2*)(dstbuf + ((((size_t)b0 * NH + head) * NWIN + n0) * HD + wd)) = v0;
            *(float2*)(dstbuf + ((((size_t)b1 * NH + head) * NWIN + n1) * HD + wd)) = v1;
        }
    }
}

// ============ proj / fc1 GEMM ============
template<int EPI>
__global__ __launch_bounds__(256, 2)
void gemm_tc(const float* __restrict__ bias,
             const float* __restrict__ resid,
             float* __restrict__ out) {
    extern __shared__ unsigned smu[];
    unsigned* sAu = smu;
    unsigned* sB  = smu + 12800;
    const float* A = (EPI == 1) ? g_ao : g_y;
    int rowbase = blockIdx.x * 128;
    int tid = threadIdx.x;
    int w = tid >> 5, lane = tid & 31;
    int g = lane >> 2, tig = lane & 3;
    int r0 = w * 16 + g;

    // ---- stage A: coalesced float4 -> cvt -> STS.128 ----
    {
        const float4* A4 = (const float4*)(A + (size_t)rowbase * 96);
        #pragma unroll
        for (int it = 0; it < 12; it++) {
            int idx = tid + it * 256;   // 3072
            int r = idx / 24, k4 = idx % 24;
            float4 v = A4[idx];
            *(uint4*)(sAu + r * 100 + k4 * 4) =
                make_uint4(f2tf(v.x), f2tf(v.y), f2tf(v.z), f2tf(v.w));
        }
    }
    // ---- stage B: copy prepacked frags ----
    {
        const uint4* s4 = (const uint4*)(g_Bp + (EPI == 1 ? 3 : 4) * 9216);
        uint4* d4 = (uint4*)sB;
        #pragma unroll
        for (int i = 0; i < 9; i++) d4[tid + i * 256] = s4[tid + i * 256];
    }
    __syncthreads();

    float d[12][4];
    #pragma unroll
    for (int nt = 0; nt < 12; nt++)
        #pragma unroll
        for (int r = 0; r < 4; r++) d[nt][r] = 0.0f;
    mma12(d, sAu, sB, r0, tig, lane);

    if (EPI == 1) {
        size_t rowdst[2];
        #pragma unroll
        for (int rr = 0; rr < 2; rr++) {
            int m = rowbase + r0 + rr * 8;
            int b_ = m / NWIN, n = m % NWIN;
            int b = b_ >> 11;
            int widx = b_ & (NWX - 1);
            int wd = widx >> 8, wh = (widx >> 4) & 15, ww = widx & 15;
            int nd = n / 49, nr = n % 49, nh2 = nr / 7, nw2 = nr % 7;
            int dp = wd * 2 + nd, hp = wh * 7 + nh2, wp = ww * 7 + nw2;
            int dd = dp + 1; if (dd >= DD) dd -= DD;
            int hh = hp + 3; if (hh >= HH) hh -= HH;
            int ww3 = wp + 3; if (ww3 >= WW2) ww3 -= WW2;
            rowdst[rr] = ((size_t)b * LTOT +
                          (size_t)(dd * (HH * WW2) + hh * WW2 + ww3)) * CD;
        }
        #pragma unroll
        for (int nt = 0; nt < 12; nt++) {
            int c = nt * 8 + tig * 2;
            float bx = bias[c], by = bias[c + 1];
            *(float2*)(g_y + rowdst[0] + c) = make_float2(d[nt][0] + bx, d[nt][1] + by);
            *(float2*)(g_y + rowdst[1] + c) = make_float2(d[nt][2] + bx, d[nt][3] + by);
        }
    } else {
        int m0 = rowbase + r0;
        #pragma unroll
        for (int nt = 0; nt < 12; nt++) {
            int c = nt * 8 + tig * 2;
            float bx = bias[c], by = bias[c + 1];
            #pragma unroll
            for (int rr = 0; rr < 2; rr++) {
                size_t o = (size_t)(m0 + rr * 8) * CD + c;
                float v0 = d[nt][rr * 2] + bx;
                float v1 = d[nt][rr * 2 + 1] + by;
                float g0 = 0.5f * v0 * (1.0f + erff(v0 * 0.70710678118654752f));
                float g1 = 0.5f * v1 * (1.0f + erff(v1 * 0.70710678118654752f));
                float2 rv = *(const float2*)(resid + o);
                *(float2*)(out + o) = make_float2(rv.x + g0, rv.y + g1);
            }
        }
    }
}

// ============ K3: tensor-core window attention ============
// smem (u32 words):
//   q_u [112][36] = 4032  @ 0        (tf32 bits)
//   k_u [104][36] = 3744  @ 4032
//   Ss  [98][108] = 10584 @ 0   (float, overlaps q_u/k_u after S phase)
//   vT  [32][108] = 3456  @ 10584    (tf32 bits)
// total = 14040 words = 56160 B -> 4 CTAs/SM
#define ATTN_SMEM (14040 * 4)
__global__ __launch_bounds__(224, 4)
void attn_kernel() {
    extern __shared__ unsigned smu[];
    unsigned* q_u = smu;
    unsigned* k_u = smu + 4032;
    float* Ss = (float*)smu;
    unsigned* vT = smu + 10584;

    int b_ = blockIdx.x;
    int head = blockIdx.y;
    int tid = threadIdx.x;
    int w = tid >> 5, lane = tid & 31;
    int g = lane >> 2, tig = lane & 3;
    size_t base = ((size_t)b_ * NH + head) * (size_t)(NWIN * HD);

    // ---- coalesced load, tf32-convert, plain-layout store ----
    {
        const float4* q4 = (const float4*)(g_q + base);
        const float4* k4 = (const float4*)(g_k + base);
        const float4* v4 = (const float4*)(g_v + base);
        for (int i4 = tid; i4 < 832; i4 += 224) {
            int n = i4 >> 3;
            int c = (i4 & 7) << 2;
            if (n < 98) {
                float4 qv = q4[i4];
                float4 kv = k4[i4];
                float4 vv = v4[i4];
                *(uint4*)(q_u + n * 36 + c) =
                    make_uint4(f2tf(qv.x), f2tf(qv.y), f2tf(qv.z), f2tf(qv.w));
                *(uint4*)(k_u + n * 36 + c) =
                    make_uint4(f2tf(kv.x), f2tf(kv.y), f2tf(kv.z), f2tf(kv.w));
                vT[(c + 0) * 108 + n] = f2tf(vv.x);
                vT[(c + 1) * 108 + n] = f2tf(vv.y);
                vT[(c + 2) * 108 + n] = f2tf(vv.z);
                vT[(c + 3) * 108 + n] = f2tf(vv.w);
            } else {
                vT[(c + 0) * 108 + n] = 0u;
                vT[(c + 1) * 108 + n] = 0u;
                vT[(c + 2) * 108 + n] = 0u;
                vT[(c + 3) * 108 + n] = 0u;
            }
        }
    }
    __syncthreads();

    int r0 = w * 16 + g;
    // ---- S = Q K^T ----
    float d[13][4];
    #pragma unroll
    for (int nt = 0; nt < 13; nt++)
        #pragma unroll
        for (int r = 0; r < 4; r++) d[nt][r] = 0.0f;
    {
        uint4 af[4];
        #pragma unroll
        for (int kt = 0; kt < 4; kt++) {
            af[kt].x = q_u[r0 * 36 + kt * 8 + tig];
            af[kt].y = q_u[(r0 + 8) * 36 + kt * 8 + tig];
            af[kt].z = q_u[r0 * 36 + kt * 8 + tig + 4];
            af[kt].w = q_u[(r0 + 8) * 36 + kt * 8 + tig + 4];
        }
        #pragma unroll
        for (int nt = 0; nt < 13; nt++) {
            #pragma unroll
            for (int kt = 0; kt < 4; kt++) {
                uint2 bf;
                bf.x = k_u[(nt * 8 + g) * 36 + kt * 8 + tig];
                bf.y = k_u[(nt * 8 + g) * 36 + kt * 8 + tig + 4];
                mma_tf32(d[nt], af[kt], bf);
            }
        }
    }
    __syncthreads();   // q/k reads done; region becomes Ss

    bool v0 = r0 < 98, v1 = (r0 + 8) < 98;
    // ---- bias/mask + exp + row-sum in registers ----
    {
        int widx = b_ & (NWX - 1);
        int cls = (((widx >> 8) == 7) << 2) | ((((widx >> 4) & 15) == 15) << 1) |
                  ((widx & 15) == 15);
        const float* bmp = g_bm + (size_t)(cls * NH + head) * (NWIN * NWIN);
        float s0 = 0.0f, s1 = 0.0f;
        #pragma unroll
        for (int nt = 0; nt < 13; nt++) {
            int c0 = nt * 8 + tig * 2;
            float e0 = 0.f, e1 = 0.f, e2 = 0.f, e3 = 0.f;
            if (c0 < 98) {
                if (v0) {
                    float2 bb = __ldg((const float2*)(bmp + r0 * 98 + c0));
                    e0 = __expf(d[nt][0] + bb.x);
                    e1 = __expf(d[nt][1] + bb.y);
                }
                if (v1) {
                    float2 bb = __ldg((const float2*)(bmp + (r0 + 8) * 98 + c0));
                    e2 = __expf(d[nt][2] + bb.x);
                    e3 = __expf(d[nt][3] + bb.y);
                }
            }
            d[nt][0] = e0; d[nt][1] = e1; d[nt][2] = e2; d[nt][3] = e3;
            s0 += e0 + e1; s1 += e2 + e3;
        }
        s0 += __shfl_xor_sync(0xffffffffu, s0, 1);
        s0 += __shfl_xor_sync(0xffffffffu, s0, 2);
        s1 += __shfl_xor_sync(0xffffffffu, s1, 1);
        s1 += __shfl_xor_sync(0xffffffffu, s1, 2);
        float i0 = v0 ? (1.0f / s0) : 0.0f;
        float i1 = v1 ? (1.0f / s1) : 0.0f;
        #pragma unroll
        for (int nt = 0; nt < 13; nt++) {
            int c0 = nt * 8 + tig * 2;
            if (v0) *(float2*)(Ss + r0 * 108 + c0) =
                make_float2(d[nt][0] * i0, d[nt][1] * i0);
            if (v1) *(float2*)(Ss + (r0 + 8) * 108 + c0) =
                make_float2(d[nt][2] * i1, d[nt][3] * i1);
        }
    }
    __syncthreads();

    // ---- O = P V ----
    {
        int rA = v0 ? r0 : 0;
        int rB = v1 ? (r0 + 8) : 0;
        unsigned mA = v0 ? 0xffffffffu : 0u;
        unsigned mB = v1 ? 0xffffffffu : 0u;
        float o[4][4];
        #pragma unroll
        for (int nt = 0; nt < 4; nt++)
            #pragma unroll
            for (int r = 0; r < 4; r++) o[nt][r] = 0.0f;
        #pragma unroll
        for (int kt = 0; kt < 13; kt++) {
            uint4 af;
            af.x = f2tf(Ss[rA * 108 + kt * 8 + tig]) & mA;
            af.y = f2tf(Ss[rB * 108 + kt * 8 + tig]) & mB;
            af.z = f2tf(Ss[rA * 108 + kt * 8 + tig + 4]) & mA;
            af.w = f2tf(Ss[rB * 108 + kt * 8 + tig + 4]) & mB;
            #pragma unroll
            for (int nt = 0; nt < 4; nt++) {
                uint2 bf;
                bf.x = vT[(nt * 8 + g) * 108 + kt * 8 + tig];
                bf.y = vT[(nt * 8 + g) * 108 + kt * 8 + tig + 4];
                mma_tf32(o[nt], af, bf);
            }
        }
        #pragma unroll
        for (int nt = 0; nt < 4; nt++) {
            int c = nt * 8 + tig * 2;
            if (v0)
                *(float2*)(g_ao + ((size_t)b_ * NWIN + r0) * CD + head * HD + c) =
                    make_float2(o[nt][0], o[nt][1]);
            if (v1)
                *(float2*)(g_ao + ((size_t)b_ * NWIN + r0 + 8) * CD + head * HD + c) =
                    make_float2(o[nt][2], o[nt][3]);
        }
    }
}

// ============ launch ============
extern "C" void kernel_launch(void* const* d_in, const int* in_sizes, int n_in,
                              void* d_out, int out_size) {
    const float* x     = (const float*)d_in[0];
    const float* mask  = (const float*)d_in[1];
    const float* n1w   = (const float*)d_in[2];
    const float* n1b   = (const float*)d_in[3];
    const float* qkvw  = (const float*)d_in[4];
    const float* qkvb  = (const float*)d_in[5];
    const float* relt  = (const float*)d_in[6];
    const float* projw = (const float*)d_in[7];
    const float* projb = (const float*)d_in[8];
    const float* fc1w  = (const float*)d_in[9];
    const float* fc1b  = (const float*)d_in[10];
    float* out = (float*)d_out;

    cudaFuncSetAttribute(attn_kernel, cudaFuncAttributeMaxDynamicSharedMemorySize, ATTN_SMEM);
    cudaFuncSetAttribute(gemm_qkv, cudaFuncAttributeMaxDynamicSharedMemorySize, GEMM_SMEM);
    cudaFuncSetAttribute(gemm_tc<1>, cudaFuncAttributeMaxDynamicSharedMemorySize, GEMM_SMEM);
    cudaFuncSetAttribute(gemm_tc<2>, cudaFuncAttributeMaxDynamicSharedMemorySize, GEMM_SMEM);

    bm_kernel<<<(8 * NH * NWIN * NWIN + 255) / 256, 256>>>(relt, mask);
    prepack_kernel<<<(5 * 9216 + 255) / 256, 256>>>(qkvw, projw, fc1w);
    gemm_qkv<<<MTOT / 128, 256, GEMM_SMEM>>>(x, n1w, n1b, qkvb);
    attn_kernel<<<dim3(BTOT, NH), 224, ATTN_SMEM>>>();
    gemm_tc<1><<<MTOT / 128, 256, GEMM_SMEM>>>(projb, nullptr, nullptr);
    gemm_tc<2><<<MTOT / 128, 256, GEMM_SMEM>>>(fc1b, x, out);
}